// round 12
// baseline (speedup 1.0000x reference)
#include <cuda_runtime.h>
#include <cuda_bf16.h>

// ESN: T=2048 steps, N=2048 reservoir, D=128 input.
// out[t] = erf(U[t] + W_res @ out[t-1]) * 1/sqrt(N),  U = input @ W_in^T
#define T_STEPS 2048
#define N_RES   2048
#define D_IN    128
#define GBLK    128          // persistent blocks (1 per SM, all co-resident)
#define ROWS_PER_BLK 16      // N_RES / GBLK
#define NTHREADS 256
#define CPT      8           // columns per thread = N_RES / NTHREADS
#define NPAIR    8           // row pairs per block (f32x2 packs 2 rows)
#define NCELL    16          // one arrival cell per row-slot (wp,ln) pair
#define CELLSTR  64          // unsigned stride between cells (256B, distinct lines)
#define INV_SQRT_N 0.022097086912079612f

__device__ float    g_U[T_STEPS * N_RES];        // input projection scratch (16 MB)
__device__ unsigned g_scount16[NCELL * CELLSTR]; // per-row-slot counters (never reset)
__device__ unsigned g_count;                     // init-barrier arrive counter
__device__ unsigned g_epoch;                     // init-barrier epoch (monotonic)

typedef unsigned long long u64;

__device__ __forceinline__ u64 pack2(float lo, float hi) {
    u64 r; asm("mov.b64 %0, {%1,%2};" : "=l"(r) : "f"(lo), "f"(hi)); return r;
}
__device__ __forceinline__ void unpack2(u64 v, float& lo, float& hi) {
    asm("mov.b64 {%0,%1}, %2;" : "=f"(lo), "=f"(hi) : "l"(v));
}
__device__ __forceinline__ void fma2(u64& acc, u64 a, u64 b) {
    asm("fma.rn.f32x2 %0, %1, %2, %0;" : "+l"(acc) : "l"(a), "l"(b));
}
__device__ __forceinline__ u64 add2(u64 a, u64 b) {
    u64 r; asm("add.rn.f32x2 %0, %1, %2;" : "=l"(r) : "l"(a), "l"(b)); return r;
}
__device__ __forceinline__ u64 shfl_xor64(u64 v, int m) {
    unsigned lo = (unsigned)v, hi = (unsigned)(v >> 32);
    lo = __shfl_xor_sync(0xffffffffu, lo, m);
    hi = __shfl_xor_sync(0xffffffffu, hi, m);
    return ((u64)hi << 32) | (u64)lo;
}
__device__ __forceinline__ unsigned ldrelax(const unsigned* p) {
    unsigned v;
    asm volatile("ld.relaxed.gpu.global.u32 %0, [%1];" : "=r"(v) : "l"(p) : "memory");
    return v;
}

// One-time grid barrier at kernel start (epoch + counter-base agreement).
__device__ __forceinline__ void grid_barrier(int tid, unsigned target) {
    __syncthreads();
    if (tid == 0) {
        unsigned prev;
        asm volatile("atom.release.gpu.global.add.u32 %0, [%1], %2;"
                     : "=r"(prev) : "l"(&g_count), "r"(1u) : "memory");
        if (prev == (unsigned)(GBLK - 1)) {
            asm volatile("st.relaxed.gpu.global.u32 [%0], %1;"
                         :: "l"(&g_count), "r"(0u) : "memory");
            asm volatile("st.release.gpu.global.u32 [%0], %1;"
                         :: "l"(&g_epoch), "r"(target) : "memory");
        } else {
            unsigned cur;
            do {
                asm volatile("ld.acquire.gpu.global.u32 %0, [%1];"
                             : "=r"(cur) : "l"(&g_epoch) : "memory");
            } while (cur != target);
        }
    }
    __syncthreads();
}

// ---------------------------------------------------------------------------
// Kernel 1: U[t][n] = sum_d input[t][d] * W_in[n][d]   (2048 x 2048 x 128)
// ---------------------------------------------------------------------------
__global__ void __launch_bounds__(256) u_gemm_kernel(
    const float* __restrict__ inp, const float* __restrict__ win)
{
    __shared__ float As[32][129];
    __shared__ float Bs[32][129];
    const int tid = threadIdx.x;
    const int t0 = blockIdx.y * 32;
    const int n0 = blockIdx.x * 32;

    #pragma unroll
    for (int i = 0; i < 4; i++) {
        int f   = tid + i * 256;
        int row = f >> 5;
        int c4  = (f & 31) << 2;
        float4 va = *(const float4*)(inp + (t0 + row) * D_IN + c4);
        float4 vb = *(const float4*)(win + (n0 + row) * D_IN + c4);
        As[row][c4] = va.x; As[row][c4 + 1] = va.y; As[row][c4 + 2] = va.z; As[row][c4 + 3] = va.w;
        Bs[row][c4] = vb.x; Bs[row][c4 + 1] = vb.y; Bs[row][c4 + 2] = vb.z; Bs[row][c4 + 3] = vb.w;
    }
    __syncthreads();

    const int tx = tid & 15, ty = tid >> 4;
    float a00 = 0.f, a01 = 0.f, a10 = 0.f, a11 = 0.f;
    #pragma unroll 16
    for (int k = 0; k < D_IN; k++) {
        float x0 = As[2 * ty][k],     x1 = As[2 * ty + 1][k];
        float y0 = Bs[2 * tx][k],     y1 = Bs[2 * tx + 1][k];
        a00 = fmaf(x0, y0, a00); a01 = fmaf(x0, y1, a01);
        a10 = fmaf(x1, y0, a10); a11 = fmaf(x1, y1, a11);
    }
    const int r = t0 + 2 * ty, c = n0 + 2 * tx;
    g_U[r * N_RES + c]           = a00;
    g_U[r * N_RES + c + 1]       = a01;
    g_U[(r + 1) * N_RES + c]     = a10;
    g_U[(r + 1) * N_RES + c + 1] = a11;
}

// ---------------------------------------------------------------------------
// Kernel 2: persistent recurrence, R8 data path + two sync refinements:
//  (1) warp-autonomous arrivals: lanes 0/1 of each warp store their row and
//      red.release.add to cell (2wp+ln). 16 cells, 128 adds/cell/step (R8's
//      proven per-line rate). Deletes the producer-side block bar entirely.
//  (2) pipelined detect: warp-0 lanes 0..15 poll their cell with batches of
//      4 independent ld.relaxed (max-combined; counter is monotonic), then
//      one fence.acq_rel.gpu on success -> sampling every ~8cyc instead of
//      once per L2 round trip. HB chain: red.release -> relaxed read ->
//      fence.acquire -> bar.sync -> all lanes' loads.
// red[] reuse without a third bar is safe: any thread's next-iteration red
// write is preceded (program order) by its post-detect bar.sync, which
// cannot release until every thread has finished this iteration's red reads.
// ---------------------------------------------------------------------------
__global__ void __launch_bounds__(NTHREADS, 1) esn_recur_kernel(
    const float* __restrict__ wres, float* __restrict__ out)
{
    __shared__ u64 red[NPAIR * NTHREADS];   // 16 KB reduction staging
    __shared__ unsigned s_cbase[NCELL];

    const int tid = threadIdx.x;
    const int bid = blockIdx.x;
    const int r0  = bid * ROWS_PER_BLK;
    const int c0  = tid * CPT;
    const int wp  = tid >> 5, ln = tid & 31;

    // Load W_res slice: w[p][c] = {W[r0+2p][c0+c], W[r0+2p+1][c0+c]}
    u64 w[NPAIR][CPT];
    #pragma unroll
    for (int p = 0; p < NPAIR; p++) {
        const float4* ra = (const float4*)(wres + (r0 + 2 * p)     * N_RES + c0);
        const float4* rb = (const float4*)(wres + (r0 + 2 * p + 1) * N_RES + c0);
        float4 a0 = ra[0], a1 = ra[1];
        float4 b0 = rb[0], b1 = rb[1];
        w[p][0] = pack2(a0.x, b0.x); w[p][1] = pack2(a0.y, b0.y);
        w[p][2] = pack2(a0.z, b0.z); w[p][3] = pack2(a0.w, b0.w);
        w[p][4] = pack2(a1.x, b1.x); w[p][5] = pack2(a1.y, b1.y);
        w[p][6] = pack2(a1.z, b1.z); w[p][7] = pack2(a1.w, b1.w);
    }

    // Snapshot quiescent per-cell counters; init barrier ensures agreement
    // before any arrival.
    if (tid < NCELL)
        s_cbase[tid] = ldrelax(&g_scount16[tid * CELLSTR]);
    unsigned e0;
    asm volatile("ld.acquire.gpu.global.u32 %0, [%1];" : "=r"(e0) : "l"(&g_epoch) : "memory");
    grid_barrier(tid, e0 + 1);

    // Step 0: lanes 0/1 of each warp handle rows 2wp,2wp+1 autonomously.
    if (ln < 2) {
        const int r = 2 * wp + ln;
        out[r0 + r] = erff(g_U[r0 + r]) * INV_SQRT_N;
        asm volatile("red.release.gpu.global.add.u32 [%0], %1;"
                     :: "l"(&g_scount16[r * CELLSTR]), "r"(1u) : "memory");
    }

    #pragma unroll 1
    for (int t = 1; t < T_STEPS; t++) {
        // Prefetch U[t] for my row (lanes 0/1 of each warp) before the wait.
        float u = 0.f;
        if (ln < 2) u = __ldg(&g_U[t * N_RES + r0 + 2 * wp + ln]);

        // Warp-0 lanes 0..15 poll their cell with pipelined relaxed probes.
        if (wp == 0 && ln < NCELL) {
            const unsigned tgt = s_cbase[ln] + (unsigned)(GBLK * t);
            const unsigned* cell = &g_scount16[ln * CELLSTR];
            for (;;) {
                unsigned a = ldrelax(cell);
                unsigned b = ldrelax(cell);
                unsigned c = ldrelax(cell);
                unsigned d = ldrelax(cell);
                unsigned m = max(max(a, b), max(c, d));
                if ((int)(m - tgt) >= 0) break;
            }
        }
        if (wp == 0)
            asm volatile("fence.acq_rel.gpu;" ::: "memory");
        __syncthreads();   // broadcast: fence happens-before all lanes' loads

        // Load my 8 x values from the previous out row (L1 bypass: remote SMs).
        const float4* xp = (const float4*)(out + (t - 1) * N_RES + c0);
        float4 xv0 = __ldcg(xp);
        float4 xv1 = __ldcg(xp + 1);
        u64 xx[CPT];
        xx[0] = pack2(xv0.x, xv0.x); xx[1] = pack2(xv0.y, xv0.y);
        xx[2] = pack2(xv0.z, xv0.z); xx[3] = pack2(xv0.w, xv0.w);
        xx[4] = pack2(xv1.x, xv1.x); xx[5] = pack2(xv1.y, xv1.y);
        xx[6] = pack2(xv1.z, xv1.z); xx[7] = pack2(xv1.w, xv1.w);

        u64 acc[NPAIR];
        #pragma unroll
        for (int p = 0; p < NPAIR; p++) acc[p] = 0ULL;
        #pragma unroll
        for (int c = 0; c < CPT; c++) {
            #pragma unroll
            for (int p = 0; p < NPAIR; p++) fma2(acc[p], w[p][c], xx[c]);
        }

        // Stage partials; warp wp reduces row-pair wp across 256 threads.
        #pragma unroll
        for (int p = 0; p < NPAIR; p++) red[p * NTHREADS + tid] = acc[p];
        __syncthreads();

        u64 s = red[wp * NTHREADS + ln];
        #pragma unroll
        for (int k = 1; k < 8; k++) s = add2(s, red[wp * NTHREADS + ln + 32 * k]);
        #pragma unroll
        for (int m = 16; m >= 1; m >>= 1) s = add2(s, shfl_xor64(s, m));
        // Every lane now holds the full {row 2wp, row 2wp+1} dot-product pair.

        // Lanes 0/1 finish their row and arrive autonomously (no block bar).
        if (ln < 2) {
            float lo, hi; unpack2(s, lo, hi);
            float pre = u + (ln == 0 ? lo : hi);
            const int r = 2 * wp + ln;
            out[t * N_RES + r0 + r] = erff(pre) * INV_SQRT_N;
            asm volatile("red.release.gpu.global.add.u32 [%0], %1;"
                         :: "l"(&g_scount16[r * CELLSTR]), "r"(1u) : "memory");
        }
        // No third __syncthreads: next iteration's post-detect bar protects red[].
    }
}

// ---------------------------------------------------------------------------
extern "C" void kernel_launch(void* const* d_in, const int* in_sizes, int n_in,
                              void* d_out, int out_size)
{
    const float* input = (const float*)d_in[0];   // (2048, 128)
    const float* w_in  = (const float*)d_in[1];   // (2048, 128)
    const float* w_res = (const float*)d_in[2];   // (2048, 2048)
    float* out = (float*)d_out;                   // (2048, 2048)

    u_gemm_kernel<<<dim3(N_RES / 32, T_STEPS / 32), 256>>>(input, w_in);
    esn_recur_kernel<<<GBLK, NTHREADS>>>(w_res, out);
}